// round 8
// baseline (speedup 1.0000x reference)
#include <cuda_runtime.h>
#include <math.h>
#include <float.h>

#define BATCH   4096
#define NPART   100
#define PSIZE   64
#define CTX     64
#define H1      256
#define H2      256
#define F3IN    320
#define F3OUT   512
#define F4OUT   256
#define F5OUT   128
#define F6OUT   32
#define HID     32
#define NLAYER  6
#define VOCAB   361
#define TSTEPS  24
#define TOPK    8

typedef unsigned long long ull;

// scratch (device globals: allowed; no runtime allocation)
__device__ float g_pooled[BATCH * H2];   // 4 MB
__device__ float g_z[BATCH * F6OUT];     // 0.5 MB

// ---------------- f32x2 packed helpers (Blackwell FFMA2 path) --------------
__device__ __forceinline__ ull ffma2(ull a, ull b, ull c) {
    ull d;
    asm("fma.rn.f32x2 %0, %1, %2, %3;" : "=l"(d) : "l"(a), "l"(b), "l"(c));
    return d;
}
__device__ __forceinline__ ull pack_dup(float v) {
    ull d;
    unsigned r = __float_as_uint(v);
    asm("mov.b64 %0, {%1, %2};" : "=l"(d) : "r"(r), "r"(r));
    return d;
}
__device__ __forceinline__ float2 unpack2(ull v) {
    unsigned lo, hi;
    asm("mov.b64 {%0, %1}, %2;" : "=r"(lo), "=r"(hi) : "l"(v));
    return make_float2(__uint_as_float(lo), __uint_as_float(hi));
}

// ---------------------------------------------------------------------------
// Kernel 1 (v3): particle encoder, wavefront-minimized.
// 1 CTA per sample, 256 thr = 8 warps. Each warp owns 12-13 private particles
// and covers the FULL 256-wide output row (8 j per lane) -> one weight-row
// load (8 wf) serves P particles instead of 5-per-half-row.
// Per-sample math identical (bias + ascending-k fma chain per (p,j)).
// ---------------------------------------------------------------------------
template<int P>
__device__ __forceinline__ void enc_pass(
    const float* __restrict__ w1, const float* __restrict__ b1,
    const float* __restrict__ w2, const float* __restrict__ b2,
    const float* xs, float* hw, int pb, int j0, float* pool)
{
    // ---- fc1: 64 -> 256 for P particles ----
    ull a[P][4];
    #pragma unroll
    for (int p = 0; p < P; p++) {
        a[p][0] = *(const ull*)(b1 + j0);
        a[p][1] = *(const ull*)(b1 + j0 + 2);
        a[p][2] = *(const ull*)(b1 + j0 + 4);
        a[p][3] = *(const ull*)(b1 + j0 + 6);
    }
    #pragma unroll 2
    for (int k = 0; k < PSIZE; k++) {
        const ulonglong2 wA = *(const ulonglong2*)(w1 + k * H1 + j0);
        const ulonglong2 wB = *(const ulonglong2*)(w1 + k * H1 + j0 + 4);
        #pragma unroll
        for (int p = 0; p < P; p++) {
            const ull xx = pack_dup(xs[(pb + p) * PSIZE + k]);
            a[p][0] = ffma2(xx, wA.x, a[p][0]);
            a[p][1] = ffma2(xx, wA.y, a[p][1]);
            a[p][2] = ffma2(xx, wB.x, a[p][2]);
            a[p][3] = ffma2(xx, wB.y, a[p][3]);
        }
    }
    #pragma unroll
    for (int p = 0; p < P; p++) {
        const float2 v0 = unpack2(a[p][0]);
        const float2 v1 = unpack2(a[p][1]);
        const float2 v2 = unpack2(a[p][2]);
        const float2 v3 = unpack2(a[p][3]);
        *(float4*)(hw + p * H1 + j0) =
            make_float4(fmaxf(v0.x, 0.f), fmaxf(v0.y, 0.f),
                        fmaxf(v1.x, 0.f), fmaxf(v1.y, 0.f));
        *(float4*)(hw + p * H1 + j0 + 4) =
            make_float4(fmaxf(v2.x, 0.f), fmaxf(v2.y, 0.f),
                        fmaxf(v3.x, 0.f), fmaxf(v3.y, 0.f));
    }
    __syncwarp();

    // ---- fc2: 256 -> 256 for P particles, pooled relu accumulate ----
    ull c[P][4];
    #pragma unroll
    for (int p = 0; p < P; p++) {
        c[p][0] = *(const ull*)(b2 + j0);
        c[p][1] = *(const ull*)(b2 + j0 + 2);
        c[p][2] = *(const ull*)(b2 + j0 + 4);
        c[p][3] = *(const ull*)(b2 + j0 + 6);
    }
    #pragma unroll 2
    for (int k = 0; k < H1; k++) {
        const ulonglong2 wA = *(const ulonglong2*)(w2 + k * H1 + j0);
        const ulonglong2 wB = *(const ulonglong2*)(w2 + k * H1 + j0 + 4);
        #pragma unroll
        for (int p = 0; p < P; p++) {
            const ull hh = pack_dup(hw[p * H1 + k]);
            c[p][0] = ffma2(hh, wA.x, c[p][0]);
            c[p][1] = ffma2(hh, wA.y, c[p][1]);
            c[p][2] = ffma2(hh, wB.x, c[p][2]);
            c[p][3] = ffma2(hh, wB.y, c[p][3]);
        }
    }
    #pragma unroll
    for (int p = 0; p < P; p++) {
        const float2 v0 = unpack2(c[p][0]);
        const float2 v1 = unpack2(c[p][1]);
        const float2 v2 = unpack2(c[p][2]);
        const float2 v3 = unpack2(c[p][3]);
        pool[0] += fmaxf(v0.x, 0.f);
        pool[1] += fmaxf(v0.y, 0.f);
        pool[2] += fmaxf(v1.x, 0.f);
        pool[3] += fmaxf(v1.y, 0.f);
        pool[4] += fmaxf(v2.x, 0.f);
        pool[5] += fmaxf(v2.y, 0.f);
        pool[6] += fmaxf(v3.x, 0.f);
        pool[7] += fmaxf(v3.y, 0.f);
    }
    __syncwarp();   // hw may be overwritten by the next pass
}

// dynamic smem: xs (100*64 floats) + per-warp h1 buffers (8 * 7 * 256 floats)
#define ENC_SMEM_FLOATS (NPART * PSIZE + 8 * 7 * H1)
#define ENC_SMEM_BYTES  (ENC_SMEM_FLOATS * 4)

__global__ __launch_bounds__(256) void enc_kernel(
    const float* __restrict__ x,
    const float* __restrict__ w1, const float* __restrict__ b1,
    const float* __restrict__ w2, const float* __restrict__ b2)
{
    extern __shared__ float sm[];
    float* xs  = sm;                    // 6400 floats
    float* h1s = sm + NPART * PSIZE;    // 8 * 7 * 256 floats

    const int b   = blockIdx.x;
    const int tid = threadIdx.x;

    {
        const float4* xg  = (const float4*)(x + (size_t)b * (NPART * PSIZE));
        float4*       xs4 = (float4*)xs;
        for (int i = tid; i < NPART * PSIZE / 4; i += 256) xs4[i] = xg[i];
    }
    __syncthreads();

    const int w  = tid >> 5;
    const int ln = tid & 31;
    const int j0 = ln * 8;
    const int start = (w < 4) ? 13 * w : 52 + 12 * (w - 4);
    const int cnt   = (w < 4) ? 13 : 12;
    float* hw = h1s + w * 7 * H1;

    float pool[8] = {0.f, 0.f, 0.f, 0.f, 0.f, 0.f, 0.f, 0.f};

    if (cnt == 13) {
        enc_pass<7>(w1, b1, w2, b2, xs, hw, start,     j0, pool);
        enc_pass<6>(w1, b1, w2, b2, xs, hw, start + 7, j0, pool);
    } else {
        enc_pass<6>(w1, b1, w2, b2, xs, hw, start,     j0, pool);
        enc_pass<6>(w1, b1, w2, b2, xs, hw, start + 6, j0, pool);
    }

    // cross-warp pool reduction (reuse xs region)
    __syncthreads();
    #pragma unroll
    for (int q = 0; q < 8; q++) xs[w * H1 + j0 + q] = pool[q];
    __syncthreads();
    float ssum = 0.f;
    #pragma unroll
    for (int ww = 0; ww < 8; ww++) ssum += xs[ww * H1 + tid];
    g_pooled[(size_t)b * H2 + tid] = ssum * 0.01f;
}

// ---------------------------------------------------------------------------
// Kernel 2: fc3..fc6 head. 8 samples per CTA, 256 threads. (unchanged)
// ---------------------------------------------------------------------------
__global__ __launch_bounds__(256) void head_kernel(
    const float* __restrict__ c,
    const float* __restrict__ w3, const float* __restrict__ b3,
    const float* __restrict__ w4, const float* __restrict__ b4,
    const float* __restrict__ w5, const float* __restrict__ b5,
    const float* __restrict__ w6, const float* __restrict__ b6)
{
    __shared__ float zin[8 * F3IN];
    __shared__ float h3 [8 * F3OUT];
    __shared__ float h4 [8 * F4OUT];
    __shared__ float h5 [8 * F5OUT];

    const int bb  = blockIdx.x * 8;
    const int tid = threadIdx.x;

    for (int i = tid; i < 8 * CTX; i += 256) {
        const int s = i >> 6, k = i & 63;
        zin[s * F3IN + k] = c[(size_t)(bb + s) * CTX + k];
    }
    for (int i = tid; i < 8 * H2; i += 256) {
        const int s = i >> 8, k = i & 255;
        zin[s * F3IN + CTX + k] = g_pooled[(size_t)(bb + s) * H2 + k];
    }
    __syncthreads();

    // fc3: 320 -> 512
    {
        const int j0 = tid * 2;
        const float2 bv = *(const float2*)(b3 + j0);
        float2 acc[8];
        #pragma unroll
        for (int s = 0; s < 8; s++) acc[s] = bv;
        #pragma unroll 4
        for (int k = 0; k < F3IN; k++) {
            const float2 w = *(const float2*)(w3 + k * F3OUT + j0);
            #pragma unroll
            for (int s = 0; s < 8; s++) {
                const float zv = zin[s * F3IN + k];
                acc[s].x = fmaf(zv, w.x, acc[s].x);
                acc[s].y = fmaf(zv, w.y, acc[s].y);
            }
        }
        #pragma unroll
        for (int s = 0; s < 8; s++) {
            float2 r;
            r.x = fmaxf(acc[s].x, 0.f);
            r.y = fmaxf(acc[s].y, 0.f);
            *(float2*)(h3 + s * F3OUT + j0) = r;
        }
    }
    __syncthreads();

    // fc4: 512 -> 256
    {
        const float bv = b4[tid];
        float acc[8];
        #pragma unroll
        for (int s = 0; s < 8; s++) acc[s] = bv;
        #pragma unroll 8
        for (int k = 0; k < F3OUT; k++) {
            const float w = w4[k * F4OUT + tid];
            #pragma unroll
            for (int s = 0; s < 8; s++) acc[s] = fmaf(h3[s * F3OUT + k], w, acc[s]);
        }
        #pragma unroll
        for (int s = 0; s < 8; s++) h4[s * F4OUT + tid] = fmaxf(acc[s], 0.f);
    }
    __syncthreads();

    // fc5: 256 -> 128
    {
        const int j  = tid & 127;
        const int sh = tid >> 7;
        const float bv = b5[j];
        float acc[4];
        #pragma unroll
        for (int i = 0; i < 4; i++) acc[i] = bv;
        #pragma unroll 8
        for (int k = 0; k < F4OUT; k++) {
            const float w = w5[k * F5OUT + j];
            #pragma unroll
            for (int i = 0; i < 4; i++)
                acc[i] = fmaf(h4[(sh * 4 + i) * F4OUT + k], w, acc[i]);
        }
        #pragma unroll
        for (int i = 0; i < 4; i++) h5[(sh * 4 + i) * F5OUT + j] = fmaxf(acc[i], 0.f);
    }
    __syncthreads();

    // fc6: 128 -> 32
    {
        const int s = tid >> 5, j = tid & 31;
        float acc = b6[j];
        #pragma unroll 8
        for (int k = 0; k < F5OUT; k++)
            acc = fmaf(h5[s * F5OUT + k], w6[k * F6OUT + j], acc);
        g_z[(size_t)(bb + s) * F6OUT + j] = fmaxf(acc, 0.f);
    }
}

// ---------------------------------------------------------------------------
// Kernel 3 (v2): LSTM rollout, warp = 4 samples, CTA = 4 warps = 16 samples.
// All per-sample state private to one warp -> __syncwarp only, no CTA
// barriers in the rollout. Weight loads amortized over 4 samples.
// Per-sample math bitwise identical to the passing R7 kernel.
// ---------------------------------------------------------------------------
__device__ __forceinline__ float sigmoidf_(float v) { return 1.0f / (1.0f + expf(-v)); }

#define LW     4   // warps per CTA
#define LSAMP  4   // samples per warp

__global__ __launch_bounds__(128) void lstm_kernel(
    const float* __restrict__ hidden0, const float* __restrict__ cell0,
    const float* __restrict__ wih, const float* __restrict__ whh,
    const float* __restrict__ bih, const float* __restrict__ bhh,
    const float* __restrict__ w10, const float* __restrict__ b10,
    float* __restrict__ out)
{
    __shared__ float hst[LW][NLAYER][LSAMP][HID];   // 12288 B
    __shared__ float cst[LW][NLAYER][LSAMP][HID];   // 12288 B
    __shared__ float xb [LW][LSAMP][HID];           //  2048 B
    __shared__ float gt [LW][LSAMP][4 * HID];       //  8192 B
    __shared__ float bsum[NLAYER * 4 * HID];        //  3072 B

    const int tid   = threadIdx.x;
    const int w     = tid >> 5;
    const int ln    = tid & 31;
    const int bbase = blockIdx.x * (LW * LSAMP);

    for (int i = tid; i < NLAYER * 4 * HID; i += 128) bsum[i] = bih[i] + bhh[i];
    for (int i = tid; i < LW * NLAYER * LSAMP * HID; i += 128) {
        const int u  = i & 31;
        const int s  = (i >> 5) & 3;
        const int wl = i >> 7;           // w*6 + l
        const int l  = wl % NLAYER;
        const int ww = wl / NLAYER;
        const int gb = bbase + ww * LSAMP + s;
        (&hst[0][0][0][0])[i] = hidden0[(size_t)l * BATCH * HID + (size_t)gb * HID + u];
        (&cst[0][0][0][0])[i] = cell0  [(size_t)l * BATCH * HID + (size_t)gb * HID + u];
    }
    for (int i = tid; i < LW * LSAMP * HID; i += 128) {
        const int u  = i & 31;
        const int s  = (i >> 5) & 3;
        const int ww = i >> 7;
        (&xb[0][0][0])[i] = g_z[(size_t)(bbase + ww * LSAMP + s) * F6OUT + u];
    }
    __syncthreads();

    const float* inp = &xb[w][0][0];    // [LSAMP][HID] contiguous

    for (int t = 0; t < TSTEPS; t++) {
        const float* lin = inp;
        for (int l = 0; l < NLAYER; l++) {
            // gates: lane owns cols 4*ln..4*ln+3 for 4 samples
            float4 a[LSAMP];
            {
                const float4 bv = *(const float4*)(bsum + l * 128 + ln * 4);
                #pragma unroll
                for (int s = 0; s < LSAMP; s++) a[s] = bv;
            }
            const float* Wi = wih + (size_t)l * HID * 128;
            const float* Wh = whh + (size_t)l * HID * 128;
            const float* hl = &hst[w][l][0][0];
            #pragma unroll 4
            for (int k = 0; k < HID; k++) {
                const float4 wv = *(const float4*)(Wi + k * 128 + ln * 4);
                #pragma unroll
                for (int s = 0; s < LSAMP; s++) {
                    const float xv = lin[s * HID + k];
                    a[s].x = fmaf(xv, wv.x, a[s].x);
                    a[s].y = fmaf(xv, wv.y, a[s].y);
                    a[s].z = fmaf(xv, wv.z, a[s].z);
                    a[s].w = fmaf(xv, wv.w, a[s].w);
                }
            }
            #pragma unroll 4
            for (int k = 0; k < HID; k++) {
                const float4 wv = *(const float4*)(Wh + k * 128 + ln * 4);
                #pragma unroll
                for (int s = 0; s < LSAMP; s++) {
                    const float hv = hl[s * HID + k];
                    a[s].x = fmaf(hv, wv.x, a[s].x);
                    a[s].y = fmaf(hv, wv.y, a[s].y);
                    a[s].z = fmaf(hv, wv.z, a[s].z);
                    a[s].w = fmaf(hv, wv.w, a[s].w);
                }
            }
            #pragma unroll
            for (int s = 0; s < LSAMP; s++)
                *(float4*)(&gt[w][s][ln * 4]) = a[s];
            __syncwarp();

            // cell/hidden update: lane = unit ln, 4 samples
            #pragma unroll
            for (int s = 0; s < LSAMP; s++) {
                const float ig = sigmoidf_(gt[w][s][ln]);
                const float fg = sigmoidf_(gt[w][s][32 + ln]);
                const float gg = tanhf    (gt[w][s][64 + ln]);
                const float og = sigmoidf_(gt[w][s][96 + ln]);
                const float cn = fmaf(fg, cst[w][l][s][ln], ig * gg);
                cst[w][l][s][ln] = cn;
                hst[w][l][s][ln] = og * tanhf(cn);
            }
            __syncwarp();
            lin = &hst[w][l][0][0];
        }
        inp = &hst[w][NLAYER - 1][0][0];   // scan carry

        // logits for 4 samples (w10 loads shared), then top-8 from registers
        {
            float vals[LSAMP][12];
            #pragma unroll
            for (int i = 0; i < 12; i++) {
                const int v = ln + i * 32;
                const float bv = (v < VOCAB) ? b10[v] : -FLT_MAX;
                #pragma unroll
                for (int s = 0; s < LSAMP; s++) vals[s][i] = bv;
            }
            const float* h5v = &hst[w][NLAYER - 1][0][0];
            #pragma unroll 2
            for (int k = 0; k < HID; k++) {
                float wreg[12];
                #pragma unroll
                for (int i = 0; i < 11; i++) wreg[i] = w10[k * VOCAB + ln + i * 32];
                wreg[11] = (ln + 352 < VOCAB) ? w10[k * VOCAB + ln + 352] : 0.f;
                #pragma unroll
                for (int s = 0; s < LSAMP; s++) {
                    const float hv = h5v[s * HID + k];
                    #pragma unroll
                    for (int i = 0; i < 11; i++)
                        vals[s][i] = fmaf(hv, wreg[i], vals[s][i]);
                    if (ln + 352 < VOCAB)
                        vals[s][11] = fmaf(hv, wreg[11], vals[s][11]);
                }
            }

            #pragma unroll
            for (int s = 0; s < LSAMP; s++) {
                const int obase = (bbase + w * LSAMP + s) * (TSTEPS * TOPK) + t * TOPK;
                #pragma unroll
                for (int r = 0; r < TOPK; r++) {
                    float bvv = vals[s][0]; int bi = 0;
                    #pragma unroll
                    for (int i = 1; i < 12; i++)
                        if (vals[s][i] > bvv) { bvv = vals[s][i]; bi = i; }
                    int gi = ln + bi * 32;
                    #pragma unroll
                    for (int off = 16; off; off >>= 1) {
                        const float ov = __shfl_xor_sync(0xffffffffu, bvv, off);
                        const int   oi = __shfl_xor_sync(0xffffffffu, gi,  off);
                        if (ov > bvv || (ov == bvv && oi < gi)) { bvv = ov; gi = oi; }
                    }
                    if (ln == 0) out[obase + r] = (float)gi;
                    if ((gi & 31) == ln) vals[s][gi >> 5] = -FLT_MAX;
                }
            }
        }
        // no CTA barrier needed: all state is warp-private
    }
}

// ---------------------------------------------------------------------------
// Host: identify inputs BY SIZE (element count or bytes auto-detected).
// ---------------------------------------------------------------------------
extern "C" void kernel_launch(void* const* d_in, const int* in_sizes, int n_in,
                              void* d_out, int out_size)
{
    const float* C_=0; const float* X_=0; const float* HID0_=0; const float* CELL0_=0;
    const float* W1_=0; const float* B1_=0; const float* W2_=0; const float* B2_=0;
    const float* W3_=0; const float* B3_=0; const float* W4_=0; const float* B4_=0;
    const float* W5_=0; const float* B5_=0; const float* W6_=0; const float* B6_=0;
    const float* BIH_=0; const float* BHH_=0; const float* W10_=0; const float* B10_=0;

    int div = 1;
    for (int i = 0; i < n_in; i++) {
        if (in_sizes[i] == 26214400) { div = 1; break; }
        if (in_sizes[i] == 104857600) { div = 4; break; }
    }

    int n256 = 0, n786 = 0, n768 = 0, n24k = 0;
    int idx24k[2] = {-1, -1};
    int idx_fc10w = -1, idx_fc1w = -1;

    for (int i = 0; i < n_in; i++) {
        const long s = (long)in_sizes[i] / div;
        const float* p = (const float*)d_in[i];
        switch (s) {
            case 262144:   C_  = p; break;
            case 26214400: X_  = p; break;
            case 786432:   if (n786++ == 0) HID0_ = p; else CELL0_ = p; break;
            case 16384:    W1_ = p; idx_fc1w = i; break;
            case 256:      { if (n256 == 0) B1_ = p; else if (n256 == 1) B2_ = p;
                             else B4_ = p; n256++; } break;
            case 65536:    W2_ = p; break;
            case 163840:   W3_ = p; break;
            case 512:      B3_ = p; break;
            case 131072:   W4_ = p; break;
            case 32768:    W5_ = p; break;
            case 128:      B5_ = p; break;
            case 4096:     W6_ = p; break;
            case 32:       B6_ = p; break;
            case 24576:    if (n24k < 2) idx24k[n24k] = i; n24k++; break;
            case 768:      if (n768++ == 0) BIH_ = p; else BHH_ = p; break;
            case 11552:    W10_ = p; idx_fc10w = i; break;
            case 361:      B10_ = p; break;
            default: break; // particle_size scalar etc.
        }
    }

    const float* WIH_ = 0; const float* WHH_ = 0;
    if (n24k >= 2) {
        const bool alpha = (idx_fc10w >= 0 && idx_fc1w >= 0 && idx_fc10w < idx_fc1w);
        const int wih_idx = alpha ? idx24k[1] : idx24k[0];
        const int whh_idx = alpha ? idx24k[0] : idx24k[1];
        WIH_ = (const float*)d_in[wih_idx];
        WHH_ = (const float*)d_in[whh_idx];
    }

    if (!C_ || !X_ || !HID0_ || !CELL0_ || !W1_ || !B1_ || !W2_ || !B2_ ||
        !W3_ || !B3_ || !W4_ || !B4_ || !W5_ || !B5_ || !W6_ || !B6_ ||
        !WIH_ || !WHH_ || !BIH_ || !BHH_ || !W10_ || !B10_) {
        C_    = (const float*)d_in[0];  X_    = (const float*)d_in[1];
        HID0_ = (const float*)d_in[2];  CELL0_= (const float*)d_in[3];
        W1_   = (const float*)d_in[4];  B1_   = (const float*)d_in[5];
        W2_   = (const float*)d_in[6];  B2_   = (const float*)d_in[7];
        W3_   = (const float*)d_in[8];  B3_   = (const float*)d_in[9];
        W4_   = (const float*)d_in[10]; B4_   = (const float*)d_in[11];
        W5_   = (const float*)d_in[12]; B5_   = (const float*)d_in[13];
        W6_   = (const float*)d_in[14]; B6_   = (const float*)d_in[15];
        WIH_  = (const float*)d_in[16]; WHH_  = (const float*)d_in[17];
        BIH_  = (const float*)d_in[18]; BHH_  = (const float*)d_in[19];
        W10_  = (const float*)d_in[20]; B10_  = (const float*)d_in[21];
    }
    (void)out_size;

    // allow >48KB dynamic smem for the encoder (host attribute set; capture-safe)
    cudaFuncSetAttribute(enc_kernel,
                         cudaFuncAttributeMaxDynamicSharedMemorySize,
                         ENC_SMEM_BYTES);

    enc_kernel<<<BATCH, 256, ENC_SMEM_BYTES>>>(X_, W1_, B1_, W2_, B2_);
    head_kernel<<<BATCH / 8, 256>>>(C_, W3_, B3_, W4_, B4_, W5_, B5_, W6_, B6_);
    lstm_kernel<<<BATCH / (LW * LSAMP), 128>>>(HID0_, CELL0_, WIH_, WHH_,
                                               BIH_, BHH_, W10_, B10_,
                                               (float*)d_out);
}

// round 9
// speedup vs baseline: 1.0589x; 1.0589x over previous
#include <cuda_runtime.h>
#include <math.h>
#include <float.h>

#define BATCH   4096
#define NPART   100
#define PSIZE   64
#define CTX     64
#define H1      256
#define H2      256
#define F3IN    320
#define F3OUT   512
#define F4OUT   256
#define F5OUT   128
#define F6OUT   32
#define HID     32
#define NLAYER  6
#define VOCAB   361
#define TSTEPS  24
#define TOPK    8

typedef unsigned long long ull;

// scratch (device globals: allowed; no runtime allocation)
__device__ float g_pooled[BATCH * H2];       // 4 MB
__device__ float g_z[BATCH * F6OUT];         // 0.5 MB
__device__ float g_w1t[PSIZE * H1];          // 64 KB   [k2][j][2] k-pair interleave
__device__ float g_w2t[H1 * H1];             // 256 KB  [k2][j][2]

// ---------------- f32x2 packed helpers (Blackwell FFMA2 path) --------------
__device__ __forceinline__ ull ffma2(ull a, ull b, ull c) {
    ull d;
    asm("fma.rn.f32x2 %0, %1, %2, %3;" : "=l"(d) : "l"(a), "l"(b), "l"(c));
    return d;
}
__device__ __forceinline__ float2 unpack2(ull v) {
    unsigned lo, hi;
    asm("mov.b64 {%0, %1}, %2;" : "=r"(lo), "=r"(hi) : "l"(v));
    return make_float2(__uint_as_float(lo), __uint_as_float(hi));
}

// ---------------------------------------------------------------------------
// Kernel 0: weight transpose into k-pair-interleaved layout.
//   wt[k2*512 + j*2 + e] = w[(2*k2+e)*256 + j]
// ---------------------------------------------------------------------------
__global__ void prep_kernel(const float* __restrict__ w1,
                            const float* __restrict__ w2)
{
    const int i = blockIdx.x * blockDim.x + threadIdx.x;
    if (i < (PSIZE / 2) * H1) {
        const int k2 = i >> 8, j = i & 255;
        g_w1t[k2 * 512 + j * 2]     = w1[(2 * k2)     * H1 + j];
        g_w1t[k2 * 512 + j * 2 + 1] = w1[(2 * k2 + 1) * H1 + j];
    }
    if (i < (H1 / 2) * H1) {
        const int k2 = i >> 8, j = i & 255;
        g_w2t[k2 * 512 + j * 2]     = w2[(2 * k2)     * H1 + j];
        g_w2t[k2 * 512 + j * 2 + 1] = w2[(2 * k2 + 1) * H1 + j];
    }
}

// ---------------------------------------------------------------------------
// Kernel 1 (v4): particle encoder, k-pair packed FFMA2.
// 1 CTA/sample, 256 thr = 8 warps = 4 groups x 2 j-roles (128 j each).
// Each lane: 4 j outputs; accumulator ull = (sum over even k, sum over odd k).
// Per k-pair: 1x 32B weight load + 1x 8B broadcast LDS per particle.
// Group g owns particles [g*25, g*25+25) in passes of 7,6,6,6.
// ---------------------------------------------------------------------------
#define ENC_SMEM_FLOATS (NPART * PSIZE + 4 * 7 * H1)
#define ENC_SMEM_BYTES  (ENC_SMEM_FLOATS * 4)

template<int P>
__device__ __forceinline__ void enc_pass(
    const float* __restrict__ b1, const float* __restrict__ b2,
    const float* xs, float* hg, int pb, int j0, float* pool)
{
    __syncthreads();   // hg free (previous pass fully consumed by both roles)

    // ---- fc1: 64 -> 256 (this role's 128 j) for P particles ----
    ull a[P][4];
    #pragma unroll
    for (int p = 0; p < P; p++)
        a[p][0] = a[p][1] = a[p][2] = a[p][3] = 0ULL;

    #pragma unroll 4
    for (int k2 = 0; k2 < PSIZE / 2; k2++) {
        const ulonglong4 wv = *(const ulonglong4*)(g_w1t + k2 * 512 + j0 * 2);
        #pragma unroll
        for (int p = 0; p < P; p++) {
            const ull xx = *(const ull*)(xs + (pb + p) * PSIZE + 2 * k2); // (xe,xo)
            a[p][0] = ffma2(xx, wv.x, a[p][0]);
            a[p][1] = ffma2(xx, wv.y, a[p][1]);
            a[p][2] = ffma2(xx, wv.z, a[p][2]);
            a[p][3] = ffma2(xx, wv.w, a[p][3]);
        }
    }
    {
        const float4 bv = *(const float4*)(b1 + j0);
        #pragma unroll
        for (int p = 0; p < P; p++) {
            const float2 v0 = unpack2(a[p][0]);
            const float2 v1 = unpack2(a[p][1]);
            const float2 v2 = unpack2(a[p][2]);
            const float2 v3 = unpack2(a[p][3]);
            *(float4*)(hg + p * H1 + j0) = make_float4(
                fmaxf(bv.x + v0.x + v0.y, 0.f),
                fmaxf(bv.y + v1.x + v1.y, 0.f),
                fmaxf(bv.z + v2.x + v2.y, 0.f),
                fmaxf(bv.w + v3.x + v3.y, 0.f));
        }
    }
    __syncthreads();   // both roles' h1 halves visible

    // ---- fc2: 256 -> 256 (this role's 128 j), pooled relu accumulate ----
    ull c[P][4];
    #pragma unroll
    for (int p = 0; p < P; p++)
        c[p][0] = c[p][1] = c[p][2] = c[p][3] = 0ULL;

    #pragma unroll 4
    for (int k2 = 0; k2 < H1 / 2; k2++) {
        const ulonglong4 wv = *(const ulonglong4*)(g_w2t + k2 * 512 + j0 * 2);
        #pragma unroll
        for (int p = 0; p < P; p++) {
            const ull hh = *(const ull*)(hg + p * H1 + 2 * k2);  // (he,ho) bcast
            c[p][0] = ffma2(hh, wv.x, c[p][0]);
            c[p][1] = ffma2(hh, wv.y, c[p][1]);
            c[p][2] = ffma2(hh, wv.z, c[p][2]);
            c[p][3] = ffma2(hh, wv.w, c[p][3]);
        }
    }
    {
        const float4 bv = *(const float4*)(b2 + j0);
        #pragma unroll
        for (int p = 0; p < P; p++) {
            const float2 v0 = unpack2(c[p][0]);
            const float2 v1 = unpack2(c[p][1]);
            const float2 v2 = unpack2(c[p][2]);
            const float2 v3 = unpack2(c[p][3]);
            pool[0] += fmaxf(bv.x + v0.x + v0.y, 0.f);
            pool[1] += fmaxf(bv.y + v1.x + v1.y, 0.f);
            pool[2] += fmaxf(bv.z + v2.x + v2.y, 0.f);
            pool[3] += fmaxf(bv.w + v3.x + v3.y, 0.f);
        }
    }
}

__global__ __launch_bounds__(256) void enc_kernel(
    const float* __restrict__ x,
    const float* __restrict__ b1, const float* __restrict__ b2)
{
    extern __shared__ float sm[];
    float* xs  = sm;                    // 6400 floats
    float* h1s = sm + NPART * PSIZE;    // 4 groups * 7 * 256 floats

    const int b   = blockIdx.x;
    const int tid = threadIdx.x;

    {
        const float4* xg  = (const float4*)(x + (size_t)b * (NPART * PSIZE));
        float4*       xs4 = (float4*)xs;
        for (int i = tid; i < NPART * PSIZE / 4; i += 256) xs4[i] = xg[i];
    }

    const int w  = tid >> 5;
    const int ln = tid & 31;
    const int g  = w >> 1;              // group 0..3 (25 particles each)
    const int r  = w & 1;               // j-role: 0 -> j[0:128), 1 -> j[128:256)
    const int j0 = r * 128 + ln * 4;
    const int pb = g * 25;
    float* hg = h1s + g * 7 * H1;

    float pool[4] = {0.f, 0.f, 0.f, 0.f};

    enc_pass<7>(b1, b2, xs, hg, pb,      j0, pool);
    enc_pass<6>(b1, b2, xs, hg, pb + 7,  j0, pool);
    enc_pass<6>(b1, b2, xs, hg, pb + 13, j0, pool);
    enc_pass<6>(b1, b2, xs, hg, pb + 19, j0, pool);

    // cross-group pool reduction (reuse xs region; w = 2*g + r)
    __syncthreads();
    #pragma unroll
    for (int q = 0; q < 4; q++) xs[w * 128 + ln * 4 + q] = pool[q];
    __syncthreads();
    {
        const int j  = tid;
        const int rr = j >> 7, jj = j & 127;
        float ssum = 0.f;
        #pragma unroll
        for (int gg = 0; gg < 4; gg++) ssum += xs[(2 * gg + rr) * 128 + jj];
        g_pooled[(size_t)b * H2 + j] = ssum * 0.01f;
    }
}

// ---------------------------------------------------------------------------
// Kernel 2: fc3..fc6 head. 8 samples per CTA, 256 threads. (unchanged)
// ---------------------------------------------------------------------------
__global__ __launch_bounds__(256) void head_kernel(
    const float* __restrict__ c,
    const float* __restrict__ w3, const float* __restrict__ b3,
    const float* __restrict__ w4, const float* __restrict__ b4,
    const float* __restrict__ w5, const float* __restrict__ b5,
    const float* __restrict__ w6, const float* __restrict__ b6)
{
    __shared__ float zin[8 * F3IN];
    __shared__ float h3 [8 * F3OUT];
    __shared__ float h4 [8 * F4OUT];
    __shared__ float h5 [8 * F5OUT];

    const int bb  = blockIdx.x * 8;
    const int tid = threadIdx.x;

    for (int i = tid; i < 8 * CTX; i += 256) {
        const int s = i >> 6, k = i & 63;
        zin[s * F3IN + k] = c[(size_t)(bb + s) * CTX + k];
    }
    for (int i = tid; i < 8 * H2; i += 256) {
        const int s = i >> 8, k = i & 255;
        zin[s * F3IN + CTX + k] = g_pooled[(size_t)(bb + s) * H2 + k];
    }
    __syncthreads();

    // fc3: 320 -> 512
    {
        const int j0 = tid * 2;
        const float2 bv = *(const float2*)(b3 + j0);
        float2 acc[8];
        #pragma unroll
        for (int s = 0; s < 8; s++) acc[s] = bv;
        #pragma unroll 4
        for (int k = 0; k < F3IN; k++) {
            const float2 w = *(const float2*)(w3 + k * F3OUT + j0);
            #pragma unroll
            for (int s = 0; s < 8; s++) {
                const float zv = zin[s * F3IN + k];
                acc[s].x = fmaf(zv, w.x, acc[s].x);
                acc[s].y = fmaf(zv, w.y, acc[s].y);
            }
        }
        #pragma unroll
        for (int s = 0; s < 8; s++) {
            float2 r;
            r.x = fmaxf(acc[s].x, 0.f);
            r.y = fmaxf(acc[s].y, 0.f);
            *(float2*)(h3 + s * F3OUT + j0) = r;
        }
    }
    __syncthreads();

    // fc4: 512 -> 256
    {
        const float bv = b4[tid];
        float acc[8];
        #pragma unroll
        for (int s = 0; s < 8; s++) acc[s] = bv;
        #pragma unroll 8
        for (int k = 0; k < F3OUT; k++) {
            const float w = w4[k * F4OUT + tid];
            #pragma unroll
            for (int s = 0; s < 8; s++) acc[s] = fmaf(h3[s * F3OUT + k], w, acc[s]);
        }
        #pragma unroll
        for (int s = 0; s < 8; s++) h4[s * F4OUT + tid] = fmaxf(acc[s], 0.f);
    }
    __syncthreads();

    // fc5: 256 -> 128
    {
        const int j  = tid & 127;
        const int sh = tid >> 7;
        const float bv = b5[j];
        float acc[4];
        #pragma unroll
        for (int i = 0; i < 4; i++) acc[i] = bv;
        #pragma unroll 8
        for (int k = 0; k < F4OUT; k++) {
            const float w = w5[k * F5OUT + j];
            #pragma unroll
            for (int i = 0; i < 4; i++)
                acc[i] = fmaf(h4[(sh * 4 + i) * F4OUT + k], w, acc[i]);
        }
        #pragma unroll
        for (int i = 0; i < 4; i++) h5[(sh * 4 + i) * F5OUT + j] = fmaxf(acc[i], 0.f);
    }
    __syncthreads();

    // fc6: 128 -> 32
    {
        const int s = tid >> 5, j = tid & 31;
        float acc = b6[j];
        #pragma unroll 8
        for (int k = 0; k < F5OUT; k++)
            acc = fmaf(h5[s * F5OUT + k], w6[k * F6OUT + j], acc);
        g_z[(size_t)(bb + s) * F6OUT + j] = fmaxf(acc, 0.f);
    }
}

// ---------------------------------------------------------------------------
// Kernel 3: LSTM rollout (R7 version restored — R8's warp-private variant
// regressed ~450us). 8 samples/CTA, 256 threads, 512 CTAs.
// ---------------------------------------------------------------------------
__device__ __forceinline__ float sigmoidf_(float v) { return 1.0f / (1.0f + expf(-v)); }

__global__ __launch_bounds__(256) void lstm_kernel(
    const float* __restrict__ hidden0, const float* __restrict__ cell0,
    const float* __restrict__ wih, const float* __restrict__ whh,
    const float* __restrict__ bih, const float* __restrict__ bhh,
    const float* __restrict__ w10, const float* __restrict__ b10,
    float* __restrict__ out)
{
    __shared__ float hst[NLAYER * 8 * HID];
    __shared__ float cst[NLAYER * 8 * HID];
    __shared__ float xb [8 * HID];
    __shared__ float gsm[8 * 128];
    __shared__ float lsm[8 * 368];
    __shared__ float bsum[NLAYER * 128];

    const int bbase = blockIdx.x * 8;
    const int tid   = threadIdx.x;

    for (int i = tid; i < NLAYER * 8 * HID; i += 256) {
        const int l = i >> 8;
        const int r = i & 255;
        hst[i] = hidden0[(size_t)l * BATCH * HID + (size_t)bbase * HID + r];
        cst[i] = cell0  [(size_t)l * BATCH * HID + (size_t)bbase * HID + r];
    }
    for (int i = tid; i < 8 * HID; i += 256) xb[i] = g_z[(size_t)bbase * HID + i];
    for (int i = tid; i < NLAYER * 128; i += 256) bsum[i] = bih[i] + bhh[i];
    __syncthreads();

    const int jg = tid & 31, sg = tid >> 5;
    const int j0 = jg * 4;
    const int lane = tid & 31, warp = tid >> 5;

    const float* inp = xb;   // scan carry

    for (int t = 0; t < TSTEPS; t++) {
        const float* lin = inp;
        for (int l = 0; l < NLAYER; l++) {
            float4 a = *(const float4*)(bsum + l * 128 + j0);
            const float* Wi = wih + (size_t)l * HID * 128;
            const float* Wh = whh + (size_t)l * HID * 128;
            const float* ip = lin + sg * HID;
            const float* hp = hst + l * 8 * HID + sg * HID;
            #pragma unroll
            for (int k = 0; k < HID; k++) {
                const float4 w = *(const float4*)(Wi + k * 128 + j0);
                const float xv = ip[k];
                a.x = fmaf(xv, w.x, a.x); a.y = fmaf(xv, w.y, a.y);
                a.z = fmaf(xv, w.z, a.z); a.w = fmaf(xv, w.w, a.w);
            }
            #pragma unroll
            for (int k = 0; k < HID; k++) {
                const float4 w = *(const float4*)(Wh + k * 128 + j0);
                const float hv = hp[k];
                a.x = fmaf(hv, w.x, a.x); a.y = fmaf(hv, w.y, a.y);
                a.z = fmaf(hv, w.z, a.z); a.w = fmaf(hv, w.w, a.w);
            }
            *(float4*)(gsm + sg * 128 + j0) = a;
            __syncthreads();

            {
                const int s = tid >> 5, u = tid & 31;
                const float ig = sigmoidf_(gsm[s * 128 + u]);
                const float fg = sigmoidf_(gsm[s * 128 + 32 + u]);
                const float gg = tanhf    (gsm[s * 128 + 64 + u]);
                const float og = sigmoidf_(gsm[s * 128 + 96 + u]);
                const int ci = l * 8 * HID + s * HID + u;
                const float cn = fmaf(fg, cst[ci], ig * gg);
                cst[ci] = cn;
                hst[ci] = og * tanhf(cn);
            }
            __syncthreads();
            lin = hst + l * 8 * HID;
        }
        inp = hst + 5 * 8 * HID;   // carry to next timestep

        // logits
        {
            const float* h5v = hst + 5 * 8 * HID;
            const int v  = tid;
            const int v2 = tid + 256;
            const bool has2 = (v2 < VOCAB);
            float acc[8], acc2[8];
            const float bv  = b10[v];
            const float bv2 = has2 ? b10[v2] : 0.f;
            #pragma unroll
            for (int s = 0; s < 8; s++) { acc[s] = bv; acc2[s] = bv2; }
            #pragma unroll
            for (int k = 0; k < HID; k++) {
                const float w  = w10[k * VOCAB + v];
                const float w2 = has2 ? w10[k * VOCAB + v2] : 0.f;
                #pragma unroll
                for (int s = 0; s < 8; s++) {
                    const float hv = h5v[s * HID + k];
                    acc[s]  = fmaf(hv, w,  acc[s]);
                    acc2[s] = fmaf(hv, w2, acc2[s]);
                }
            }
            #pragma unroll
            for (int s = 0; s < 8; s++) {
                lsm[s * 368 + v] = acc[s];
                if (has2) lsm[s * 368 + v2] = acc2[s];
            }
        }
        __syncthreads();

        // top-8: one warp per sample, stable tie-break (lower index wins)
        {
            const int s = warp;
            float vals[12];
            #pragma unroll
            for (int i = 0; i < 12; i++) {
                const int idx = lane + i * 32;
                vals[i] = (idx < VOCAB) ? lsm[s * 368 + idx] : -FLT_MAX;
            }
            const int obase = (bbase + s) * (TSTEPS * TOPK) + t * TOPK;
            #pragma unroll
            for (int r = 0; r < TOPK; r++) {
                float bvv = vals[0]; int bi = 0;
                #pragma unroll
                for (int i = 1; i < 12; i++)
                    if (vals[i] > bvv) { bvv = vals[i]; bi = i; }
                int gi = lane + bi * 32;
                #pragma unroll
                for (int off = 16; off; off >>= 1) {
                    const float ov = __shfl_xor_sync(0xffffffffu, bvv, off);
                    const int   oi = __shfl_xor_sync(0xffffffffu, gi,  off);
                    if (ov > bvv || (ov == bvv && oi < gi)) { bvv = ov; gi = oi; }
                }
                if (lane == 0) out[obase + r] = (float)gi;
                if ((gi & 31) == lane) vals[gi >> 5] = -FLT_MAX;
            }
        }
        __syncthreads();
    }
}

// ---------------------------------------------------------------------------
// Host: identify inputs BY SIZE (element count or bytes auto-detected).
// ---------------------------------------------------------------------------
extern "C" void kernel_launch(void* const* d_in, const int* in_sizes, int n_in,
                              void* d_out, int out_size)
{
    const float* C_=0; const float* X_=0; const float* HID0_=0; const float* CELL0_=0;
    const float* W1_=0; const float* B1_=0; const float* W2_=0; const float* B2_=0;
    const float* W3_=0; const float* B3_=0; const float* W4_=0; const float* B4_=0;
    const float* W5_=0; const float* B5_=0; const float* W6_=0; const float* B6_=0;
    const float* BIH_=0; const float* BHH_=0; const float* W10_=0; const float* B10_=0;

    int div = 1;
    for (int i = 0; i < n_in; i++) {
        if (in_sizes[i] == 26214400) { div = 1; break; }
        if (in_sizes[i] == 104857600) { div = 4; break; }
    }

    int n256 = 0, n786 = 0, n768 = 0, n24k = 0;
    int idx24k[2] = {-1, -1};
    int idx_fc10w = -1, idx_fc1w = -1;

    for (int i = 0; i < n_in; i++) {
        const long s = (long)in_sizes[i] / div;
        const float* p = (const float*)d_in[i];
        switch (s) {
            case 262144:   C_  = p; break;
            case 26214400: X_  = p; break;
            case 786432:   if (n786++ == 0) HID0_ = p; else CELL0_ = p; break;
            case 16384:    W1_ = p; idx_fc1w = i; break;
            case 256:      { if (n256 == 0) B1_ = p; else if (n256 == 1) B2_ = p;
                             else B4_ = p; n256++; } break;
            case 65536:    W2_ = p; break;
            case 163840:   W3_ = p; break;
            case 512:      B3_ = p; break;
            case 131072:   W4_ = p; break;
            case 32768:    W5_ = p; break;
            case 128:      B5_ = p; break;
            case 4096:     W6_ = p; break;
            case 32:       B6_ = p; break;
            case 24576:    if (n24k < 2) idx24k[n24k] = i; n24k++; break;
            case 768:      if (n768++ == 0) BIH_ = p; else BHH_ = p; break;
            case 11552:    W10_ = p; idx_fc10w = i; break;
            case 361:      B10_ = p; break;
            default: break; // particle_size scalar etc.
        }
    }

    const float* WIH_ = 0; const float* WHH_ = 0;
    if (n24k >= 2) {
        const bool alpha = (idx_fc10w >= 0 && idx_fc1w >= 0 && idx_fc10w < idx_fc1w);
        const int wih_idx = alpha ? idx24k[1] : idx24k[0];
        const int whh_idx = alpha ? idx24k[0] : idx24k[1];
        WIH_ = (const float*)d_in[wih_idx];
        WHH_ = (const float*)d_in[whh_idx];
    }

    if (!C_ || !X_ || !HID0_ || !CELL0_ || !W1_ || !B1_ || !W2_ || !B2_ ||
        !W3_ || !B3_ || !W4_ || !B4_ || !W5_ || !B5_ || !W6_ || !B6_ ||
        !WIH_ || !WHH_ || !BIH_ || !BHH_ || !W10_ || !B10_) {
        C_    = (const float*)d_in[0];  X_    = (const float*)d_in[1];
        HID0_ = (const float*)d_in[2];  CELL0_= (const float*)d_in[3];
        W1_   = (const float*)d_in[4];  B1_   = (const float*)d_in[5];
        W2_   = (const float*)d_in[6];  B2_   = (const float*)d_in[7];
        W3_   = (const float*)d_in[8];  B3_   = (const float*)d_in[9];
        W4_   = (const float*)d_in[10]; B4_   = (const float*)d_in[11];
        W5_   = (const float*)d_in[12]; B5_   = (const float*)d_in[13];
        W6_   = (const float*)d_in[14]; B6_   = (const float*)d_in[15];
        WIH_  = (const float*)d_in[16]; WHH_  = (const float*)d_in[17];
        BIH_  = (const float*)d_in[18]; BHH_  = (const float*)d_in[19];
        W10_  = (const float*)d_in[20]; B10_  = (const float*)d_in[21];
    }
    (void)out_size;

    cudaFuncSetAttribute(enc_kernel,
                         cudaFuncAttributeMaxDynamicSharedMemorySize,
                         ENC_SMEM_BYTES);

    prep_kernel<<<128, 256>>>(W1_, W2_);
    enc_kernel<<<BATCH, 256, ENC_SMEM_BYTES>>>(X_, B1_, B2_);
    head_kernel<<<BATCH / 8, 256>>>(C_, W3_, B3_, W4_, B4_, W5_, B5_, W6_, B6_);
    lstm_kernel<<<BATCH / 8, 256>>>(HID0_, CELL0_, WIH_, WHH_, BIH_, BHH_,
                                    W10_, B10_, (float*)d_out);
}

// round 10
// speedup vs baseline: 1.2136x; 1.1462x over previous
#include <cuda_runtime.h>
#include <math.h>
#include <float.h>

#define BATCH   4096
#define NPART   100
#define PSIZE   64
#define CTX     64
#define H1      256
#define H2      256
#define F3IN    320
#define F3OUT   512
#define F4OUT   256
#define F5OUT   128
#define F6OUT   32
#define HID     32
#define NLAYER  6
#define VOCAB   361
#define TSTEPS  24
#define TOPK    8

typedef unsigned long long ull;

// scratch (device globals: allowed; no runtime allocation)
__device__ float g_pooled[BATCH * H2];   // 4 MB
__device__ float g_z[BATCH * F6OUT];     // 0.5 MB

// ---------------- f32x2 packed helpers (Blackwell FFMA2 path) --------------
__device__ __forceinline__ ull ffma2(ull a, ull b, ull c) {
    ull d;
    asm("fma.rn.f32x2 %0, %1, %2, %3;" : "=l"(d) : "l"(a), "l"(b), "l"(c));
    return d;
}
__device__ __forceinline__ ull pack_dup(float v) {
    ull d;
    unsigned r = __float_as_uint(v);
    asm("mov.b64 %0, {%1, %2};" : "=l"(d) : "r"(r), "r"(r));
    return d;
}
__device__ __forceinline__ float2 unpack2(ull v) {
    unsigned lo, hi;
    asm("mov.b64 {%0, %1}, %2;" : "=r"(lo), "=r"(hi) : "l"(v));
    return make_float2(__uint_as_float(lo), __uint_as_float(hi));
}

// ---------------------------------------------------------------------------
// Kernel 1: particle encoder (R7 version verbatim — best measured: 1.69ms).
// ---------------------------------------------------------------------------
__global__ __launch_bounds__(256) void enc_kernel(
    const float* __restrict__ x,
    const float* __restrict__ w1, const float* __restrict__ b1,
    const float* __restrict__ w2, const float* __restrict__ b2)
{
    __shared__ float  xs[20 * PSIZE];    //  5120 B (current 20-particle chunk)
    __shared__ float2 h1d[20 * H1];      // 40960 B (h1 duplicated (v,v))

    const int b   = blockIdx.x;
    const int tid = threadIdx.x;
    const int jg  = tid & 63;
    const int pg  = tid >> 6;
    const int j0  = jg * 4;
    const int lp0 = pg * 5;

    const ull b1v01 = *(const ull*)(b1 + j0);
    const ull b1v23 = *(const ull*)(b1 + j0 + 2);
    const ull b2v01 = *(const ull*)(b2 + j0);
    const ull b2v23 = *(const ull*)(b2 + j0 + 2);

    float pool0 = 0.f, pool1 = 0.f, pool2 = 0.f, pool3 = 0.f;

    for (int chunk = 0; chunk < 5; chunk++) {
        {
            const float4* xg  = (const float4*)(x + (size_t)b * (NPART * PSIZE)
                                                + (size_t)chunk * 20 * PSIZE);
            float4* xs4 = (float4*)xs;
            for (int i = tid; i < 20 * PSIZE / 4; i += 256) xs4[i] = xg[i];
        }
        __syncthreads();

        // ---- fc1: 64 -> 256 over 5 particles ----
        ull a01[5], a23[5];
        #pragma unroll
        for (int p = 0; p < 5; p++) { a01[p] = b1v01; a23[p] = b1v23; }

        #pragma unroll 4
        for (int k = 0; k < PSIZE; k++) {
            const ulonglong2 w = *(const ulonglong2*)(w1 + k * H1 + j0);
            #pragma unroll
            for (int p = 0; p < 5; p++) {
                const ull xx = pack_dup(xs[(lp0 + p) * PSIZE + k]);
                a01[p] = ffma2(xx, w.x, a01[p]);
                a23[p] = ffma2(xx, w.y, a23[p]);
            }
        }
        #pragma unroll
        for (int p = 0; p < 5; p++) {
            const float2 v01 = unpack2(a01[p]);
            const float2 v23 = unpack2(a23[p]);
            float2* hr = h1d + (lp0 + p) * H1 + j0;
            const float r0 = fmaxf(v01.x, 0.f);
            const float r1 = fmaxf(v01.y, 0.f);
            const float r2 = fmaxf(v23.x, 0.f);
            const float r3 = fmaxf(v23.y, 0.f);
            hr[0] = make_float2(r0, r0);
            hr[1] = make_float2(r1, r1);
            hr[2] = make_float2(r2, r2);
            hr[3] = make_float2(r3, r3);
        }
        __syncthreads();

        // ---- fc2: 256 -> 256 over 5 particles, pooled relu accumulate ----
        ull c01[5], c23[5];
        #pragma unroll
        for (int p = 0; p < 5; p++) { c01[p] = b2v01; c23[p] = b2v23; }

        #pragma unroll 4
        for (int k = 0; k < H1; k++) {
            const ulonglong2 w = *(const ulonglong2*)(w2 + k * H1 + j0);
            #pragma unroll
            for (int p = 0; p < 5; p++) {
                const ull hh = *(const ull*)(h1d + (lp0 + p) * H1 + k); // (h,h)
                c01[p] = ffma2(hh, w.x, c01[p]);
                c23[p] = ffma2(hh, w.y, c23[p]);
            }
        }
        #pragma unroll
        for (int p = 0; p < 5; p++) {
            const float2 v01 = unpack2(c01[p]);
            const float2 v23 = unpack2(c23[p]);
            pool0 += fmaxf(v01.x, 0.f);
            pool1 += fmaxf(v01.y, 0.f);
            pool2 += fmaxf(v23.x, 0.f);
            pool3 += fmaxf(v23.y, 0.f);
        }
        __syncthreads();
    }

    {
        float* rb = (float*)h1d;
        rb[pg * H1 + j0 + 0] = pool0;
        rb[pg * H1 + j0 + 1] = pool1;
        rb[pg * H1 + j0 + 2] = pool2;
        rb[pg * H1 + j0 + 3] = pool3;
        __syncthreads();
        const float s = (rb[tid] + rb[256 + tid] + rb[512 + tid] + rb[768 + tid]) * 0.01f;
        g_pooled[(size_t)b * H2 + tid] = s;
    }
}

// ---------------------------------------------------------------------------
// Kernel 2: fc3..fc6 head. 8 samples per CTA, 256 threads. (unchanged)
// ---------------------------------------------------------------------------
__global__ __launch_bounds__(256) void head_kernel(
    const float* __restrict__ c,
    const float* __restrict__ w3, const float* __restrict__ b3,
    const float* __restrict__ w4, const float* __restrict__ b4,
    const float* __restrict__ w5, const float* __restrict__ b5,
    const float* __restrict__ w6, const float* __restrict__ b6)
{
    __shared__ float zin[8 * F3IN];
    __shared__ float h3 [8 * F3OUT];
    __shared__ float h4 [8 * F4OUT];
    __shared__ float h5 [8 * F5OUT];

    const int bb  = blockIdx.x * 8;
    const int tid = threadIdx.x;

    for (int i = tid; i < 8 * CTX; i += 256) {
        const int s = i >> 6, k = i & 63;
        zin[s * F3IN + k] = c[(size_t)(bb + s) * CTX + k];
    }
    for (int i = tid; i < 8 * H2; i += 256) {
        const int s = i >> 8, k = i & 255;
        zin[s * F3IN + CTX + k] = g_pooled[(size_t)(bb + s) * H2 + k];
    }
    __syncthreads();

    // fc3: 320 -> 512
    {
        const int j0 = tid * 2;
        const float2 bv = *(const float2*)(b3 + j0);
        float2 acc[8];
        #pragma unroll
        for (int s = 0; s < 8; s++) acc[s] = bv;
        #pragma unroll 4
        for (int k = 0; k < F3IN; k++) {
            const float2 w = *(const float2*)(w3 + k * F3OUT + j0);
            #pragma unroll
            for (int s = 0; s < 8; s++) {
                const float zv = zin[s * F3IN + k];
                acc[s].x = fmaf(zv, w.x, acc[s].x);
                acc[s].y = fmaf(zv, w.y, acc[s].y);
            }
        }
        #pragma unroll
        for (int s = 0; s < 8; s++) {
            float2 r;
            r.x = fmaxf(acc[s].x, 0.f);
            r.y = fmaxf(acc[s].y, 0.f);
            *(float2*)(h3 + s * F3OUT + j0) = r;
        }
    }
    __syncthreads();

    // fc4: 512 -> 256
    {
        const float bv = b4[tid];
        float acc[8];
        #pragma unroll
        for (int s = 0; s < 8; s++) acc[s] = bv;
        #pragma unroll 8
        for (int k = 0; k < F3OUT; k++) {
            const float w = w4[k * F4OUT + tid];
            #pragma unroll
            for (int s = 0; s < 8; s++) acc[s] = fmaf(h3[s * F3OUT + k], w, acc[s]);
        }
        #pragma unroll
        for (int s = 0; s < 8; s++) h4[s * F4OUT + tid] = fmaxf(acc[s], 0.f);
    }
    __syncthreads();

    // fc5: 256 -> 128
    {
        const int j  = tid & 127;
        const int sh = tid >> 7;
        const float bv = b5[j];
        float acc[4];
        #pragma unroll
        for (int i = 0; i < 4; i++) acc[i] = bv;
        #pragma unroll 8
        for (int k = 0; k < F4OUT; k++) {
            const float w = w5[k * F5OUT + j];
            #pragma unroll
            for (int i = 0; i < 4; i++)
                acc[i] = fmaf(h4[(sh * 4 + i) * F4OUT + k], w, acc[i]);
        }
        #pragma unroll
        for (int i = 0; i < 4; i++) h5[(sh * 4 + i) * F5OUT + j] = fmaxf(acc[i], 0.f);
    }
    __syncthreads();

    // fc6: 128 -> 32
    {
        const int s = tid >> 5, j = tid & 31;
        float acc = b6[j];
        #pragma unroll 8
        for (int k = 0; k < F5OUT; k++)
            acc = fmaf(h5[s * F5OUT + k], w6[k * F6OUT + j], acc);
        g_z[(size_t)(bb + s) * F6OUT + j] = fmaxf(acc, 0.f);
    }
}

// ---------------------------------------------------------------------------
// Kernel 3 (v4): LSTM rollout with SAMPLE-PAIRED f32x2 gates.
// 8 samples/CTA as 4 pairs; 8 warps: warp w -> pair (w>>1), col-half (w&1).
// Each lane: 2 gate cols x 2 samples (2 ull accumulators).
// Weight load = float2/lane (2wf vs 4wf); one 8B LDS feeds both samples.
// Per-sample fma chain bitwise identical to R7 (bias, asc-k Wi, asc-k Wh).
// State layouts are pair-interleaved: [..][k][2] with e = sample parity.
// ---------------------------------------------------------------------------
__device__ __forceinline__ float sigmoidf_(float v) { return 1.0f / (1.0f + expf(-v)); }

__global__ __launch_bounds__(256) void lstm_kernel(
    const float* __restrict__ hidden0, const float* __restrict__ cell0,
    const float* __restrict__ wih, const float* __restrict__ whh,
    const float* __restrict__ bih, const float* __restrict__ bhh,
    const float* __restrict__ w10, const float* __restrict__ b10,
    float* __restrict__ out)
{
    // pair-interleaved: index [l][p][k][e] = l*256 + p*64 + k*2 + e
    __shared__ float hst[NLAYER * 256];   // 6144 B
    __shared__ float cst[NLAYER * 256];   // 6144 B
    __shared__ float xb [256];            // 1024 B  [p][k][e]
    __shared__ float gtb[4 * 256];        // 4096 B  [p][col][e]
    __shared__ float lsm[8 * 368];        // 11776 B
    __shared__ float bsum[NLAYER * 128];  // 3072 B

    const int bbase = blockIdx.x * 8;
    const int tid   = threadIdx.x;

    for (int i = tid; i < NLAYER * 256; i += 256) {
        const int l = i >> 8;
        const int p = (i >> 6) & 3;
        const int k = (i >> 1) & 31;
        const int e = i & 1;
        const size_t gofs = (size_t)l * BATCH * HID + (size_t)(bbase + 2 * p + e) * HID + k;
        hst[i] = hidden0[gofs];
        cst[i] = cell0[gofs];
    }
    for (int i = tid; i < 256; i += 256) {
        const int p = (i >> 6) & 3;
        const int k = (i >> 1) & 31;
        const int e = i & 1;
        xb[i] = g_z[(size_t)(bbase + 2 * p + e) * F6OUT + k];
    }
    for (int i = tid; i < NLAYER * 128; i += 256) bsum[i] = bih[i] + bhh[i];
    __syncthreads();

    const int ln   = tid & 31;
    const int w    = tid >> 5;
    const int pw   = w >> 1;            // pair this warp computes gates for
    const int half = w & 1;             // col half
    const int j0   = half * 64 + ln * 2;

    const float* inp = xb;   // scan carry (pair layout)

    for (int t = 0; t < TSTEPS; t++) {
        const float* lin = inp;
        for (int l = 0; l < NLAYER; l++) {
            // gates: lane owns cols j0, j0+1 for pair pw (both samples packed)
            ull gA = pack_dup(bsum[l * 128 + j0]);
            ull gB = pack_dup(bsum[l * 128 + j0 + 1]);
            const float* Wi = wih + (size_t)l * HID * 128;
            const float* Wh = whh + (size_t)l * HID * 128;
            const float* ip = lin + pw * 64;
            const float* hp = hst + l * 256 + pw * 64;
            #pragma unroll 8
            for (int k = 0; k < HID; k++) {
                const float2 wv = *(const float2*)(Wi + k * 128 + j0);
                const ull xx = *(const ull*)(ip + k * 2);   // (x_s0, x_s1)
                gA = ffma2(pack_dup(wv.x), xx, gA);
                gB = ffma2(pack_dup(wv.y), xx, gB);
            }
            #pragma unroll 8
            for (int k = 0; k < HID; k++) {
                const float2 wv = *(const float2*)(Wh + k * 128 + j0);
                const ull hh = *(const ull*)(hp + k * 2);   // (h_s0, h_s1)
                gA = ffma2(pack_dup(wv.x), hh, gA);
                gB = ffma2(pack_dup(wv.y), hh, gB);
            }
            {
                ulonglong2 st; st.x = gA; st.y = gB;
                *(ulonglong2*)(gtb + pw * 256 + j0 * 2) = st;  // 16B aligned
            }
            __syncthreads();

            // cell/hidden update: warp = sample s, lane = unit u
            {
                const int s = w, u = ln;
                const int p = s >> 1, e = s & 1;
                const float* gp = gtb + p * 256 + e;
                const float ig = sigmoidf_(gp[u * 2]);
                const float fg = sigmoidf_(gp[(32 + u) * 2]);
                const float gg = tanhf    (gp[(64 + u) * 2]);
                const float og = sigmoidf_(gp[(96 + u) * 2]);
                const int ci = l * 256 + p * 64 + u * 2 + e;
                const float cn = fmaf(fg, cst[ci], ig * gg);
                cst[ci] = cn;
                hst[ci] = og * tanhf(cn);
            }
            __syncthreads();
            lin = hst + l * 256;
        }
        inp = hst + 5 * 256;   // carry to next timestep

        // logits (R7 structure; h read via pair indexing)
        {
            const float* h5v = hst + 5 * 256;
            const int v  = tid;
            const int v2 = tid + 256;
            const bool has2 = (v2 < VOCAB);
            float acc[8], acc2[8];
            const float bv  = b10[v];
            const float bv2 = has2 ? b10[v2] : 0.f;
            #pragma unroll
            for (int s = 0; s < 8; s++) { acc[s] = bv; acc2[s] = bv2; }
            #pragma unroll
            for (int k = 0; k < HID; k++) {
                const float wv  = w10[k * VOCAB + v];
                const float wv2 = has2 ? w10[k * VOCAB + v2] : 0.f;
                #pragma unroll
                for (int s = 0; s < 8; s++) {
                    const float hv = h5v[(s >> 1) * 64 + k * 2 + (s & 1)];
                    acc[s]  = fmaf(hv, wv,  acc[s]);
                    acc2[s] = fmaf(hv, wv2, acc2[s]);
                }
            }
            #pragma unroll
            for (int s = 0; s < 8; s++) {
                lsm[s * 368 + v] = acc[s];
                if (has2) lsm[s * 368 + v2] = acc2[s];
            }
        }
        __syncthreads();

        // top-8: one warp per sample, stable tie-break (lower index wins)
        {
            const int s = w;
            float vals[12];
            #pragma unroll
            for (int i = 0; i < 12; i++) {
                const int idx = ln + i * 32;
                vals[i] = (idx < VOCAB) ? lsm[s * 368 + idx] : -FLT_MAX;
            }
            const int obase = (bbase + s) * (TSTEPS * TOPK) + t * TOPK;
            #pragma unroll
            for (int r = 0; r < TOPK; r++) {
                float bvv = vals[0]; int bi = 0;
                #pragma unroll
                for (int i = 1; i < 12; i++)
                    if (vals[i] > bvv) { bvv = vals[i]; bi = i; }
                int gi = ln + bi * 32;
                #pragma unroll
                for (int off = 16; off; off >>= 1) {
                    const float ov = __shfl_xor_sync(0xffffffffu, bvv, off);
                    const int   oi = __shfl_xor_sync(0xffffffffu, gi,  off);
                    if (ov > bvv || (ov == bvv && oi < gi)) { bvv = ov; gi = oi; }
                }
                if (ln == 0) out[obase + r] = (float)gi;
                if ((gi & 31) == ln) vals[gi >> 5] = -FLT_MAX;
            }
        }
        __syncthreads();
    }
}

// ---------------------------------------------------------------------------
// Host: identify inputs BY SIZE (element count or bytes auto-detected).
// ---------------------------------------------------------------------------
extern "C" void kernel_launch(void* const* d_in, const int* in_sizes, int n_in,
                              void* d_out, int out_size)
{
    const float* C_=0; const float* X_=0; const float* HID0_=0; const float* CELL0_=0;
    const float* W1_=0; const float* B1_=0; const float* W2_=0; const float* B2_=0;
    const float* W3_=0; const float* B3_=0; const float* W4_=0; const float* B4_=0;
    const float* W5_=0; const float* B5_=0; const float* W6_=0; const float* B6_=0;
    const float* BIH_=0; const float* BHH_=0; const float* W10_=0; const float* B10_=0;

    int div = 1;
    for (int i = 0; i < n_in; i++) {
        if (in_sizes[i] == 26214400) { div = 1; break; }
        if (in_sizes[i] == 104857600) { div = 4; break; }
    }

    int n256 = 0, n786 = 0, n768 = 0, n24k = 0;
    int idx24k[2] = {-1, -1};
    int idx_fc10w = -1, idx_fc1w = -1;

    for (int i = 0; i < n_in; i++) {
        const long s = (long)in_sizes[i] / div;
        const float* p = (const float*)d_in[i];
        switch (s) {
            case 262144:   C_  = p; break;
            case 26214400: X_  = p; break;
            case 786432:   if (n786++ == 0) HID0_ = p; else CELL0_ = p; break;
            case 16384:    W1_ = p; idx_fc1w = i; break;
            case 256:      { if (n256 == 0) B1_ = p; else if (n256 == 1) B2_ = p;
                             else B4_ = p; n256++; } break;
            case 65536:    W2_ = p; break;
            case 163840:   W3_ = p; break;
            case 512:      B3_ = p; break;
            case 131072:   W4_ = p; break;
            case 32768:    W5_ = p; break;
            case 128:      B5_ = p; break;
            case 4096:     W6_ = p; break;
            case 32:       B6_ = p; break;
            case 24576:    if (n24k < 2) idx24k[n24k] = i; n24k++; break;
            case 768:      if (n768++ == 0) BIH_ = p; else BHH_ = p; break;
            case 11552:    W10_ = p; idx_fc10w = i; break;
            case 361:      B10_ = p; break;
            default: break; // particle_size scalar etc.
        }
    }

    const float* WIH_ = 0; const float* WHH_ = 0;
    if (n24k >= 2) {
        const bool alpha = (idx_fc10w >= 0 && idx_fc1w >= 0 && idx_fc10w < idx_fc1w);
        const int wih_idx = alpha ? idx24k[1] : idx24k[0];
        const int whh_idx = alpha ? idx24k[0] : idx24k[1];
        WIH_ = (const float*)d_in[wih_idx];
        WHH_ = (const float*)d_in[whh_idx];
    }

    if (!C_ || !X_ || !HID0_ || !CELL0_ || !W1_ || !B1_ || !W2_ || !B2_ ||
        !W3_ || !B3_ || !W4_ || !B4_ || !W5_ || !B5_ || !W6_ || !B6_ ||
        !WIH_ || !WHH_ || !BIH_ || !BHH_ || !W10_ || !B10_) {
        C_    = (const float*)d_in[0];  X_    = (const float*)d_in[1];
        HID0_ = (const float*)d_in[2];  CELL0_= (const float*)d_in[3];
        W1_   = (const float*)d_in[4];  B1_   = (const float*)d_in[5];
        W2_   = (const float*)d_in[6];  B2_   = (const float*)d_in[7];
        W3_   = (const float*)d_in[8];  B3_   = (const float*)d_in[9];
        W4_   = (const float*)d_in[10]; B4_   = (const float*)d_in[11];
        W5_   = (const float*)d_in[12]; B5_   = (const float*)d_in[13];
        W6_   = (const float*)d_in[14]; B6_   = (const float*)d_in[15];
        WIH_  = (const float*)d_in[16]; WHH_  = (const float*)d_in[17];
        BIH_  = (const float*)d_in[18]; BHH_  = (const float*)d_in[19];
        W10_  = (const float*)d_in[20]; B10_  = (const float*)d_in[21];
    }
    (void)out_size;

    enc_kernel<<<BATCH, 256>>>(X_, W1_, B1_, W2_, B2_);
    head_kernel<<<BATCH / 8, 256>>>(C_, W3_, B3_, W4_, B4_, W5_, B5_, W6_, B6_);
    lstm_kernel<<<BATCH / 8, 256>>>(HID0_, CELL0_, WIH_, WHH_, BIH_, BHH_,
                                    W10_, B10_, (float*)d_out);
}

// round 11
// speedup vs baseline: 1.2346x; 1.0173x over previous
#include <cuda_runtime.h>
#include <math.h>
#include <float.h>

#define BATCH   4096
#define NPART   100
#define PSIZE   64
#define CTX     64
#define H1      256
#define H2      256
#define F3IN    320
#define F3OUT   512
#define F4OUT   256
#define F5OUT   128
#define F6OUT   32
#define HID     32
#define NLAYER  6
#define VOCAB   361
#define TSTEPS  24
#define TOPK    8

typedef unsigned long long ull;

// scratch (device globals: allowed; no runtime allocation)
__device__ float g_pooled[BATCH * H2];   // 4 MB
__device__ float g_z[BATCH * F6OUT];     // 0.5 MB

// ---------------- f32x2 packed helpers (Blackwell FFMA2 path) --------------
__device__ __forceinline__ ull ffma2(ull a, ull b, ull c) {
    ull d;
    asm("fma.rn.f32x2 %0, %1, %2, %3;" : "=l"(d) : "l"(a), "l"(b), "l"(c));
    return d;
}
__device__ __forceinline__ ull pack_dup(float v) {
    ull d;
    unsigned r = __float_as_uint(v);
    asm("mov.b64 %0, {%1, %2};" : "=l"(d) : "r"(r), "r"(r));
    return d;
}
__device__ __forceinline__ float2 unpack2(ull v) {
    unsigned lo, hi;
    asm("mov.b64 {%0, %1}, %2;" : "=r"(lo), "=r"(hi) : "l"(v));
    return make_float2(__uint_as_float(lo), __uint_as_float(hi));
}

// ---------------------------------------------------------------------------
// Kernel 1 (v6): particle-paired encoder.
// f32x2 lanes = (particle p, particle p+1); j is per-lane scalar.
// Activations pair-interleaved in smem -> LDS.128 broadcast = 4 particles/wf.
// Weights: 2x coalesced LDG.32 per k (1 wf each) + pack_dup (ALU pipe).
// Per-(particle,j) fma chain bitwise identical to R7 (bias init, ascending k).
// 8 warps = 4 j-blocks x 2 particle-groups. Chunks of 20 particles (10 pairs).
// ---------------------------------------------------------------------------
#define XROWF 104   // floats/row of xpp:  50 pairs*2 + 4 pad  (416 B, 16-aligned)
#define HROWF 24    // floats/row of hpp:  10 pairs*2 + 4 pad  ( 96 B, 16-aligned)
#define ENC_SMEM_BYTES ((64 * XROWF + 256 * HROWF) * 4)   // 26624 + 24576 = 51200

// load 5 consecutive pair-cells starting at cell `base` from 16B-aligned row.
// PG==0: base even -> [128,128,64]; PG==1: base odd -> [64,128,128].
template<int PG>
__device__ __forceinline__ void load5(const float* row, int base, ull* px)
{
    const float* p = row + base * 2;
    if (PG == 0) {
        const ulonglong2 q0 = *(const ulonglong2*)(p);
        const ulonglong2 q1 = *(const ulonglong2*)(p + 4);
        const ull q2 = *(const ull*)(p + 8);
        px[0] = q0.x; px[1] = q0.y; px[2] = q1.x; px[3] = q1.y; px[4] = q2;
    } else {
        const ull q0 = *(const ull*)(p);
        const ulonglong2 q1 = *(const ulonglong2*)(p + 2);
        const ulonglong2 q2 = *(const ulonglong2*)(p + 6);
        px[0] = q0; px[1] = q1.x; px[2] = q1.y; px[3] = q2.x; px[4] = q2.y;
    }
}

template<int PG>
__device__ __forceinline__ void enc_chunk(
    const float* __restrict__ w1, const ull b1A, const ull b1B,
    const float* __restrict__ w2, const ull b2A, const ull b2B,
    const float* xpp, float* hpp,
    int c, int jA, int jB, float& pool0, float& pool1)
{
    const int cpp = c * 10 + PG * 5;   // global pair base for fc1 reads
    const int lpp = PG * 5;            // chunk-local pair base for hpp

    // ---- fc1: 64 -> 256 (this lane's jA, jB) for 5 pairs = 10 particles ----
    ull aA[5], aB[5];
    #pragma unroll
    for (int i = 0; i < 5; i++) { aA[i] = b1A; aB[i] = b1B; }

    #pragma unroll 4
    for (int k = 0; k < PSIZE; k++) {
        const ull wAd = pack_dup(w1[k * H1 + jA]);
        const ull wBd = pack_dup(w1[k * H1 + jB]);
        ull px[5];
        load5<PG>(xpp + k * XROWF, cpp, px);
        #pragma unroll
        for (int i = 0; i < 5; i++) {
            aA[i] = ffma2(px[i], wAd, aA[i]);
            aB[i] = ffma2(px[i], wBd, aB[i]);
        }
    }
    // relu + transposed pair store: hpp[j][pair]
    #pragma unroll
    for (int i = 0; i < 5; i++) {
        const float2 vA = unpack2(aA[i]);
        const float2 vB = unpack2(aB[i]);
        *(float2*)(hpp + jA * HROWF + (lpp + i) * 2) =
            make_float2(fmaxf(vA.x, 0.f), fmaxf(vA.y, 0.f));
        *(float2*)(hpp + jB * HROWF + (lpp + i) * 2) =
            make_float2(fmaxf(vB.x, 0.f), fmaxf(vB.y, 0.f));
    }
    __syncthreads();

    // ---- fc2: 256 -> 256, pooled relu accumulate ----
    ull cA[5], cB[5];
    #pragma unroll
    for (int i = 0; i < 5; i++) { cA[i] = b2A; cB[i] = b2B; }

    #pragma unroll 4
    for (int k = 0; k < H1; k++) {
        const ull wAd = pack_dup(w2[k * H1 + jA]);
        const ull wBd = pack_dup(w2[k * H1 + jB]);
        ull ph[5];
        load5<PG>(hpp + k * HROWF, lpp, ph);
        #pragma unroll
        for (int i = 0; i < 5; i++) {
            cA[i] = ffma2(ph[i], wAd, cA[i]);
            cB[i] = ffma2(ph[i], wBd, cB[i]);
        }
    }
    #pragma unroll
    for (int i = 0; i < 5; i++) {
        const float2 vA = unpack2(cA[i]);
        const float2 vB = unpack2(cB[i]);
        pool0 += fmaxf(vA.x, 0.f) + fmaxf(vA.y, 0.f);
        pool1 += fmaxf(vB.x, 0.f) + fmaxf(vB.y, 0.f);
    }
    __syncthreads();   // hpp reused by next chunk's fc1
}

__global__ __launch_bounds__(256) void enc_kernel(
    const float* __restrict__ x,
    const float* __restrict__ w1, const float* __restrict__ b1,
    const float* __restrict__ w2, const float* __restrict__ b2)
{
    extern __shared__ float sm[];
    float* xpp = sm;                 // [64][XROWF]  pair-interleaved x
    float* hpp = sm + 64 * XROWF;    // [256][HROWF] pair-interleaved h1 (chunk)

    const int b   = blockIdx.x;
    const int tid = threadIdx.x;

    // stage all 100 particles pair-interleaved: xpp[k][p>>1*2 + (p&1)] = x[p][k]
    for (int i = tid; i < NPART * PSIZE; i += 256) {
        const int p = i >> 6, k = i & 63;
        xpp[k * XROWF + (p >> 1) * 2 + (p & 1)] = x[(size_t)b * (NPART * PSIZE) + i];
    }
    __syncthreads();

    const int w  = tid >> 5;
    const int ln = tid & 31;
    const int jb = (w & 3) * 64;     // j-block
    const int pg = w >> 2;           // particle-group (pairs 0-4 / 5-9 of chunk)
    const int jA = jb + ln;
    const int jB = jb + 32 + ln;

    const ull b1A = pack_dup(b1[jA]);
    const ull b1B = pack_dup(b1[jB]);
    const ull b2A = pack_dup(b2[jA]);
    const ull b2B = pack_dup(b2[jB]);

    float pool0 = 0.f, pool1 = 0.f;

    if (pg == 0) {
        for (int c = 0; c < 5; c++)
            enc_chunk<0>(w1, b1A, b1B, w2, b2A, b2B, xpp, hpp, c, jA, jB, pool0, pool1);
    } else {
        for (int c = 0; c < 5; c++)
            enc_chunk<1>(w1, b1A, b1B, w2, b2A, b2B, xpp, hpp, c, jA, jB, pool0, pool1);
    }

    // merge the two particle-groups' partial pools (reuse xpp region)
    float* red = sm;
    red[pg * H1 + jA] = pool0;
    red[pg * H1 + jB] = pool1;
    __syncthreads();
    g_pooled[(size_t)b * H2 + tid] = (red[tid] + red[H1 + tid]) * 0.01f;
}

// ---------------------------------------------------------------------------
// Kernel 2: fc3..fc6 head. 8 samples per CTA, 256 threads. (unchanged)
// ---------------------------------------------------------------------------
__global__ __launch_bounds__(256) void head_kernel(
    const float* __restrict__ c,
    const float* __restrict__ w3, const float* __restrict__ b3,
    const float* __restrict__ w4, const float* __restrict__ b4,
    const float* __restrict__ w5, const float* __restrict__ b5,
    const float* __restrict__ w6, const float* __restrict__ b6)
{
    __shared__ float zin[8 * F3IN];
    __shared__ float h3 [8 * F3OUT];
    __shared__ float h4 [8 * F4OUT];
    __shared__ float h5 [8 * F5OUT];

    const int bb  = blockIdx.x * 8;
    const int tid = threadIdx.x;

    for (int i = tid; i < 8 * CTX; i += 256) {
        const int s = i >> 6, k = i & 63;
        zin[s * F3IN + k] = c[(size_t)(bb + s) * CTX + k];
    }
    for (int i = tid; i < 8 * H2; i += 256) {
        const int s = i >> 8, k = i & 255;
        zin[s * F3IN + CTX + k] = g_pooled[(size_t)(bb + s) * H2 + k];
    }
    __syncthreads();

    // fc3: 320 -> 512
    {
        const int j0 = tid * 2;
        const float2 bv = *(const float2*)(b3 + j0);
        float2 acc[8];
        #pragma unroll
        for (int s = 0; s < 8; s++) acc[s] = bv;
        #pragma unroll 4
        for (int k = 0; k < F3IN; k++) {
            const float2 w = *(const float2*)(w3 + k * F3OUT + j0);
            #pragma unroll
            for (int s = 0; s < 8; s++) {
                const float zv = zin[s * F3IN + k];
                acc[s].x = fmaf(zv, w.x, acc[s].x);
                acc[s].y = fmaf(zv, w.y, acc[s].y);
            }
        }
        #pragma unroll
        for (int s = 0; s < 8; s++) {
            float2 r;
            r.x = fmaxf(acc[s].x, 0.f);
            r.y = fmaxf(acc[s].y, 0.f);
            *(float2*)(h3 + s * F3OUT + j0) = r;
        }
    }
    __syncthreads();

    // fc4: 512 -> 256
    {
        const float bv = b4[tid];
        float acc[8];
        #pragma unroll
        for (int s = 0; s < 8; s++) acc[s] = bv;
        #pragma unroll 8
        for (int k = 0; k < F3OUT; k++) {
            const float w = w4[k * F4OUT + tid];
            #pragma unroll
            for (int s = 0; s < 8; s++) acc[s] = fmaf(h3[s * F3OUT + k], w, acc[s]);
        }
        #pragma unroll
        for (int s = 0; s < 8; s++) h4[s * F4OUT + tid] = fmaxf(acc[s], 0.f);
    }
    __syncthreads();

    // fc5: 256 -> 128
    {
        const int j  = tid & 127;
        const int sh = tid >> 7;
        const float bv = b5[j];
        float acc[4];
        #pragma unroll
        for (int i = 0; i < 4; i++) acc[i] = bv;
        #pragma unroll 8
        for (int k = 0; k < F4OUT; k++) {
            const float w = w5[k * F5OUT + j];
            #pragma unroll
            for (int i = 0; i < 4; i++)
                acc[i] = fmaf(h4[(sh * 4 + i) * F4OUT + k], w, acc[i]);
        }
        #pragma unroll
        for (int i = 0; i < 4; i++) h5[(sh * 4 + i) * F5OUT + j] = fmaxf(acc[i], 0.f);
    }
    __syncthreads();

    // fc6: 128 -> 32
    {
        const int s = tid >> 5, j = tid & 31;
        float acc = b6[j];
        #pragma unroll 8
        for (int k = 0; k < F5OUT; k++)
            acc = fmaf(h5[s * F5OUT + k], w6[k * F6OUT + j], acc);
        g_z[(size_t)(bb + s) * F6OUT + j] = fmaxf(acc, 0.f);
    }
}

// ---------------------------------------------------------------------------
// Kernel 3: LSTM rollout with sample-paired f32x2 gates (R10 version, frozen).
// ---------------------------------------------------------------------------
__device__ __forceinline__ float sigmoidf_(float v) { return 1.0f / (1.0f + expf(-v)); }

__global__ __launch_bounds__(256) void lstm_kernel(
    const float* __restrict__ hidden0, const float* __restrict__ cell0,
    const float* __restrict__ wih, const float* __restrict__ whh,
    const float* __restrict__ bih, const float* __restrict__ bhh,
    const float* __restrict__ w10, const float* __restrict__ b10,
    float* __restrict__ out)
{
    __shared__ float hst[NLAYER * 256];
    __shared__ float cst[NLAYER * 256];
    __shared__ float xb [256];
    __shared__ float gtb[4 * 256];
    __shared__ float lsm[8 * 368];
    __shared__ float bsum[NLAYER * 128];

    const int bbase = blockIdx.x * 8;
    const int tid   = threadIdx.x;

    for (int i = tid; i < NLAYER * 256; i += 256) {
        const int l = i >> 8;
        const int p = (i >> 6) & 3;
        const int k = (i >> 1) & 31;
        const int e = i & 1;
        const size_t gofs = (size_t)l * BATCH * HID + (size_t)(bbase + 2 * p + e) * HID + k;
        hst[i] = hidden0[gofs];
        cst[i] = cell0[gofs];
    }
    for (int i = tid; i < 256; i += 256) {
        const int p = (i >> 6) & 3;
        const int k = (i >> 1) & 31;
        const int e = i & 1;
        xb[i] = g_z[(size_t)(bbase + 2 * p + e) * F6OUT + k];
    }
    for (int i = tid; i < NLAYER * 128; i += 256) bsum[i] = bih[i] + bhh[i];
    __syncthreads();

    const int ln   = tid & 31;
    const int w    = tid >> 5;
    const int pw   = w >> 1;
    const int half = w & 1;
    const int j0   = half * 64 + ln * 2;

    const float* inp = xb;

    for (int t = 0; t < TSTEPS; t++) {
        const float* lin = inp;
        for (int l = 0; l < NLAYER; l++) {
            ull gA = pack_dup(bsum[l * 128 + j0]);
            ull gB = pack_dup(bsum[l * 128 + j0 + 1]);
            const float* Wi = wih + (size_t)l * HID * 128;
            const float* Wh = whh + (size_t)l * HID * 128;
            const float* ip = lin + pw * 64;
            const float* hp = hst + l * 256 + pw * 64;
            #pragma unroll 8
            for (int k = 0; k < HID; k++) {
                const float2 wv = *(const float2*)(Wi + k * 128 + j0);
                const ull xx = *(const ull*)(ip + k * 2);
                gA = ffma2(pack_dup(wv.x), xx, gA);
                gB = ffma2(pack_dup(wv.y), xx, gB);
            }
            #pragma unroll 8
            for (int k = 0; k < HID; k++) {
                const float2 wv = *(const float2*)(Wh + k * 128 + j0);
                const ull hh = *(const ull*)(hp + k * 2);
                gA = ffma2(pack_dup(wv.x), hh, gA);
                gB = ffma2(pack_dup(wv.y), hh, gB);
            }
            {
                ulonglong2 st; st.x = gA; st.y = gB;
                *(ulonglong2*)(gtb + pw * 256 + j0 * 2) = st;
            }
            __syncthreads();

            {
                const int s = w, u = ln;
                const int p = s >> 1, e = s & 1;
                const float* gp = gtb + p * 256 + e;
                const float ig = sigmoidf_(gp[u * 2]);
                const float fg = sigmoidf_(gp[(32 + u) * 2]);
                const float gg = tanhf    (gp[(64 + u) * 2]);
                const float og = sigmoidf_(gp[(96 + u) * 2]);
                const int ci = l * 256 + p * 64 + u * 2 + e;
                const float cn = fmaf(fg, cst[ci], ig * gg);
                cst[ci] = cn;
                hst[ci] = og * tanhf(cn);
            }
            __syncthreads();
            lin = hst + l * 256;
        }
        inp = hst + 5 * 256;

        // logits
        {
            const float* h5v = hst + 5 * 256;
            const int v  = tid;
            const int v2 = tid + 256;
            const bool has2 = (v2 < VOCAB);
            float acc[8], acc2[8];
            const float bv  = b10[v];
            const float bv2 = has2 ? b10[v2] : 0.f;
            #pragma unroll
            for (int s = 0; s < 8; s++) { acc[s] = bv; acc2[s] = bv2; }
            #pragma unroll
            for (int k = 0; k < HID; k++) {
                const float wv  = w10[k * VOCAB + v];
                const float wv2 = has2 ? w10[k * VOCAB + v2] : 0.f;
                #pragma unroll
                for (int s = 0; s < 8; s++) {
                    const float hv = h5v[(s >> 1) * 64 + k * 2 + (s & 1)];
                    acc[s]  = fmaf(hv, wv,  acc[s]);
                    acc2[s] = fmaf(hv, wv2, acc2[s]);
                }
            }
            #pragma unroll
            for (int s = 0; s < 8; s++) {
                lsm[s * 368 + v] = acc[s];
                if (has2) lsm[s * 368 + v2] = acc2[s];
            }
        }
        __syncthreads();

        // top-8: one warp per sample, stable tie-break (lower index wins)
        {
            const int s = w;
            float vals[12];
            #pragma unroll
            for (int i = 0; i < 12; i++) {
                const int idx = ln + i * 32;
                vals[i] = (idx < VOCAB) ? lsm[s * 368 + idx] : -FLT_MAX;
            }
            const int obase = (bbase + s) * (TSTEPS * TOPK) + t * TOPK;
            #pragma unroll
            for (int r = 0; r < TOPK; r++) {
                float bvv = vals[0]; int bi = 0;
                #pragma unroll
                for (int i = 1; i < 12; i++)
                    if (vals[i] > bvv) { bvv = vals[i]; bi = i; }
                int gi = ln + bi * 32;
                #pragma unroll
                for (int off = 16; off; off >>= 1) {
                    const float ov = __shfl_xor_sync(0xffffffffu, bvv, off);
                    const int   oi = __shfl_xor_sync(0xffffffffu, gi,  off);
                    if (ov > bvv || (ov == bvv && oi < gi)) { bvv = ov; gi = oi; }
                }
                if (ln == 0) out[obase + r] = (float)gi;
                if ((gi & 31) == ln) vals[gi >> 5] = -FLT_MAX;
            }
        }
        __syncthreads();
    }
}

// ---------------------------------------------------------------------------
// Host: identify inputs BY SIZE (element count or bytes auto-detected).
// ---------------------------------------------------------------------------
extern "C" void kernel_launch(void* const* d_in, const int* in_sizes, int n_in,
                              void* d_out, int out_size)
{
    const float* C_=0; const float* X_=0; const float* HID0_=0; const float* CELL0_=0;
    const float* W1_=0; const float* B1_=0; const float* W2_=0; const float* B2_=0;
    const float* W3_=0; const float* B3_=0; const float* W4_=0; const float* B4_=0;
    const float* W5_=0; const float* B5_=0; const float* W6_=0; const float* B6_=0;
    const float* BIH_=0; const float* BHH_=0; const float* W10_=0; const float* B10_=0;

    int div = 1;
    for (int i = 0; i < n_in; i++) {
        if (in_sizes[i] == 26214400) { div = 1; break; }
        if (in_sizes[i] == 104857600) { div = 4; break; }
    }

    int n256 = 0, n786 = 0, n768 = 0, n24k = 0;
    int idx24k[2] = {-1, -1};
    int idx_fc10w = -1, idx_fc1w = -1;

    for (int i = 0; i < n_in; i++) {
        const long s = (long)in_sizes[i] / div;
        const float* p = (const float*)d_in[i];
        switch (s) {
            case 262144:   C_  = p; break;
            case 26214400: X_  = p; break;
            case 786432:   if (n786++ == 0) HID0_ = p; else CELL0_ = p; break;
            case 16384:    W1_ = p; idx_fc1w = i; break;
            case 256:      { if (n256 == 0) B1_ = p; else if (n256 == 1) B2_ = p;
                             else B4_ = p; n256++; } break;
            case 65536:    W2_ = p; break;
            case 163840:   W3_ = p; break;
            case 512:      B3_ = p; break;
            case 131072:   W4_ = p; break;
            case 32768:    W5_ = p; break;
            case 128:      B5_ = p; break;
            case 4096:     W6_ = p; break;
            case 32:       B6_ = p; break;
            case 24576:    if (n24k < 2) idx24k[n24k] = i; n24k++; break;
            case 768:      if (n768++ == 0) BIH_ = p; else BHH_ = p; break;
            case 11552:    W10_ = p; idx_fc10w = i; break;
            case 361:      B10_ = p; break;
            default: break; // particle_size scalar etc.
        }
    }

    const float* WIH_ = 0; const float* WHH_ = 0;
    if (n24k >= 2) {
        const bool alpha = (idx_fc10w >= 0 && idx_fc1w >= 0 && idx_fc10w < idx_fc1w);
        const int wih_idx = alpha ? idx24k[1] : idx24k[0];
        const int whh_idx = alpha ? idx24k[0] : idx24k[1];
        WIH_ = (const float*)d_in[wih_idx];
        WHH_ = (const float*)d_in[whh_idx];
    }

    if (!C_ || !X_ || !HID0_ || !CELL0_ || !W1_ || !B1_ || !W2_ || !B2_ ||
        !W3_ || !B3_ || !W4_ || !B4_ || !W5_ || !B5_ || !W6_ || !B6_ ||
        !WIH_ || !WHH_ || !BIH_ || !BHH_ || !W10_ || !B10_) {
        C_    = (const float*)d_in[0];  X_    = (const float*)d_in[1];
        HID0_ = (const float*)d_in[2];  CELL0_= (const float*)d_in[3];
        W1_   = (const float*)d_in[4];  B1_   = (const float*)d_in[5];
        W2_   = (const float*)d_in[6];  B2_   = (const float*)d_in[7];
        W3_   = (const float*)d_in[8];  B3_   = (const float*)d_in[9];
        W4_   = (const float*)d_in[10]; B4_   = (const float*)d_in[11];
        W5_   = (const float*)d_in[12]; B5_   = (const float*)d_in[13];
        W6_   = (const float*)d_in[14]; B6_   = (const float*)d_in[15];
        WIH_  = (const float*)d_in[16]; WHH_  = (const float*)d_in[17];
        BIH_  = (const float*)d_in[18]; BHH_  = (const float*)d_in[19];
        W10_  = (const float*)d_in[20]; B10_  = (const float*)d_in[21];
    }
    (void)out_size;

    cudaFuncSetAttribute(enc_kernel,
                         cudaFuncAttributeMaxDynamicSharedMemorySize,
                         ENC_SMEM_BYTES);

    enc_kernel<<<BATCH, 256, ENC_SMEM_BYTES>>>(X_, W1_, B1_, W2_, B2_);
    head_kernel<<<BATCH / 8, 256>>>(C_, W3_, B3_, W4_, B4_, W5_, B5_, W6_, B6_);
    lstm_kernel<<<BATCH / 8, 256>>>(HID0_, CELL0_, WIH_, WHH_, BIH_, BHH_,
                                    W10_, B10_, (float*)d_out);
}